// round 10
// baseline (speedup 1.0000x reference)
#include <cuda_runtime.h>

#define BB 4096
#define DD 1024
#define THREADS 256
#define WARPS_PER_BLOCK (THREADS / 32)
#define NBLOCKS (BB / WARPS_PER_BLOCK)    // 512
#define CHUNKS (DD / 4 / 32)              // 8 float4 chunks per lane per row
#define EPSF 1e-8f
#define MARGIN 0.2f
#define NACC 11

// Cross-block loss accumulator. Invariant: both are 0 at kernel entry; the
// last finishing block restores them to 0, so every graph replay sees the
// same initial state. All sync is done with L2 atomics + acq_rel semantics —
// NO __threadfence (which would emit CCTL.IVALL and flush L1D per block).
__device__ float        g_loss_sum = 0.0f;
__device__ unsigned int g_done     = 0;

__global__ __launch_bounds__(THREADS, 4)   // 64-reg budget (R5 config: best so far)
void contrastive_kernel(const float* __restrict__ img,
                        const float* __restrict__ txt,
                        const int* __restrict__ cand_img,
                        const int* __restrict__ cand_txt,
                        float* __restrict__ out) {
    const int tid  = threadIdx.x;
    const int warp = tid >> 5;
    const int lane = tid & 31;
    const int b    = blockIdx.x * WARPS_PER_BLOCK + warp;   // one warp per row

    // candidate indices (converged scalar loads broadcast in L1)
    const int ct0 = cand_txt[2 * b + 0];
    const int ct1 = cand_txt[2 * b + 1];
    const int ci0 = cand_img[2 * b + 0];
    const int ci1 = cand_img[2 * b + 1];

    const float4* ib  = (const float4*)(img + (size_t)b   * DD);
    const float4* tb  = (const float4*)(txt + (size_t)b   * DD);
    const float4* tc0 = (const float4*)(txt + (size_t)ct0 * DD);
    const float4* tc1 = (const float4*)(txt + (size_t)ct1 * DD);
    const float4* ic0 = (const float4*)(img + (size_t)ci0 * DD);
    const float4* ic1 = (const float4*)(img + (size_t)ci1 * DD);

    // 0: |img_b|^2   1: |txt_b|^2   2: dot(img_b, txt_b)
    // 3: dot(img_b, txt_c0)  4: |txt_c0|^2
    // 5: dot(img_b, txt_c1)  6: |txt_c1|^2
    // 7: dot(txt_b, img_e0)  8: |img_e0|^2
    // 9: dot(txt_b, img_e1) 10: |img_e1|^2
    float acc[NACC];
    #pragma unroll
    for (int a = 0; a < NACC; a++) acc[a] = 0.0f;

    #pragma unroll
    for (int c = 0; c < CHUNKS; c++) {
        const int o = c * 32 + lane;
        float4 vi  = ib[o];
        float4 vt  = tb[o];
        float4 vt0 = tc0[o];
        float4 vt1 = tc1[o];
        float4 vi0 = ic0[o];
        float4 vi1 = ic1[o];

        acc[0]  += vi.x*vi.x  + vi.y*vi.y  + vi.z*vi.z  + vi.w*vi.w;
        acc[1]  += vt.x*vt.x  + vt.y*vt.y  + vt.z*vt.z  + vt.w*vt.w;
        acc[2]  += vi.x*vt.x  + vi.y*vt.y  + vi.z*vt.z  + vi.w*vt.w;
        acc[3]  += vi.x*vt0.x + vi.y*vt0.y + vi.z*vt0.z + vi.w*vt0.w;
        acc[4]  += vt0.x*vt0.x+ vt0.y*vt0.y+ vt0.z*vt0.z+ vt0.w*vt0.w;
        acc[5]  += vi.x*vt1.x + vi.y*vt1.y + vi.z*vt1.z + vi.w*vt1.w;
        acc[6]  += vt1.x*vt1.x+ vt1.y*vt1.y+ vt1.z*vt1.z+ vt1.w*vt1.w;
        acc[7]  += vt.x*vi0.x + vt.y*vi0.y + vt.z*vi0.z + vt.w*vi0.w;
        acc[8]  += vi0.x*vi0.x+ vi0.y*vi0.y+ vi0.z*vi0.z+ vi0.w*vi0.w;
        acc[9]  += vt.x*vi1.x + vt.y*vi1.y + vt.z*vi1.z + vt.w*vi1.w;
        acc[10] += vi1.x*vi1.x+ vi1.y*vi1.y+ vi1.z*vi1.z+ vi1.w*vi1.w;
    }

    // single warp-level reduction per row
    #pragma unroll
    for (int a = 0; a < NACC; a++) {
        float x = acc[a];
        #pragma unroll
        for (int off = 16; off > 0; off >>= 1)
            x += __shfl_xor_sync(0xFFFFFFFFu, x, off);
        acc[a] = x;
    }

    __shared__ float sloss[WARPS_PER_BLOCK];

    if (lane == 0) {
        const float ni    = sqrtf(acc[0]);   // |img_b|
        const float nt    = sqrtf(acc[1]);   // |txt_b|
        const float nprod = ni * nt;

        const float sim      = acc[2] / nprod;                      // unclamped
        const float pos_dist = 1.0f - acc[2] / fmaxf(nprod, EPSF);  // clamped

        const float dT0 = 1.0f - acc[3] / fmaxf(ni * sqrtf(acc[4]), EPSF);
        const float dT1 = 1.0f - acc[5] / fmaxf(ni * sqrtf(acc[6]), EPSF);
        const float i2t_neg = fminf(dT0, dT1);   // `d1<=d0` tie-break == min

        const float dI0 = 1.0f - acc[7] / fmaxf(nt * sqrtf(acc[8]),  EPSF);
        const float dI1 = 1.0f - acc[9] / fmaxf(nt * sqrtf(acc[10]), EPSF);
        const float t2i_neg = fminf(dI0, dI1);

        const float i2t_trip = fmaxf(pos_dist - i2t_neg + MARGIN, 0.0f);
        const float t2i_trip = fmaxf(pos_dist - t2i_neg + MARGIN, 0.0f);

        // outputs: [loss, i2t_cosine(B), t2i_cosine(B)]; cosines identical pair
        out[1 + b]      = sim;
        out[1 + BB + b] = sim;
        sloss[warp] = (i2t_trip + t2i_trip) * (1.0f / (float)BB);
    }

    __syncthreads();
    if (tid == 0) {
        float s = 0.0f;
        #pragma unroll
        for (int w = 0; w < WARPS_PER_BLOCK; w++) s += sloss[w];

        // relaxed device-scope RED into L2 (no fence, no L1 involvement)
        atomicAdd(&g_loss_sum, s);

        // acq_rel counter bump: release orders our loss-add before the bump;
        // acquire lets the last block observe every released add. No MEMBAR,
        // no CCTL.IVALL is generated for this.
        unsigned n;
        asm volatile("atom.acq_rel.gpu.add.u32 %0, [%1], %2;"
                     : "=r"(n) : "l"(&g_done), "r"(1u) : "memory");

        if (n == (unsigned)(NBLOCKS - 1)) {
            // last block: read total and reset to 0 atomically (restores the
            // zero-at-entry invariant for the next graph replay)
            unsigned tot_bits;
            asm volatile("atom.acquire.gpu.exch.b32 %0, [%1], %2;"
                         : "=r"(tot_bits) : "l"(&g_loss_sum), "r"(0u) : "memory");
            out[0] = __uint_as_float(tot_bits);
            atomicExch(&g_done, 0u);
        }
    }
}

extern "C" void kernel_launch(void* const* d_in, const int* in_sizes, int n_in,
                              void* d_out, int out_size) {
    const float* img      = (const float*)d_in[0];
    const float* txt      = (const float*)d_in[1];
    // d_in[2] = labels (identity anchors, unused), d_in[3] = locations (unused)
    const int*   cand_img = (const int*)d_in[4];
    const int*   cand_txt = (const int*)d_in[5];
    float* out = (float*)d_out;

    contrastive_kernel<<<NBLOCKS, THREADS>>>(img, txt, cand_img, cand_txt, out);
}

// round 13
// speedup vs baseline: 1.0732x; 1.0732x over previous
#include <cuda_runtime.h>
#include <cstdint>

#define BB 4096
#define DD 1024
#define THREADS 256
#define WARPS_PER_BLOCK (THREADS / 32)
#define NBLOCKS (BB / WARPS_PER_BLOCK)    // 512
#define CHUNKS (DD / 4 / 32)              // 8 float4 chunks per lane per row
#define NSRC 6
#define STAGES 3
#define EPSF 1e-8f
#define MARGIN 0.2f
#define NACC 11

// dynamic smem: [warp][stage][src][lane] float4 = 8*3*6*32*16 = 73728 B
#define SMEM_BYTES (WARPS_PER_BLOCK * STAGES * NSRC * 32 * 16)

__global__ void init_out_kernel(float* out) {
    out[0] = 0.0f;
}

__device__ __forceinline__ void cp16(uint32_t dst_smem, const float4* src) {
    asm volatile("cp.async.cg.shared.global [%0], [%1], 16;"
                 :: "r"(dst_smem), "l"(src) : "memory");
}
__device__ __forceinline__ void cp_commit() {
    asm volatile("cp.async.commit_group;" ::: "memory");
}
__device__ __forceinline__ void cp_wait1() {
    asm volatile("cp.async.wait_group 1;" ::: "memory");
}

__global__ __launch_bounds__(THREADS, 3)   // 85-reg budget; 3 blocks/SM (smem-limited)
void contrastive_kernel(const float* __restrict__ img,
                        const float* __restrict__ txt,
                        const int* __restrict__ cand_img,
                        const int* __restrict__ cand_txt,
                        float* __restrict__ out) {
    extern __shared__ float4 sbuf[];
    const int tid  = threadIdx.x;
    const int warp = tid >> 5;
    const int lane = tid & 31;
    const int b    = blockIdx.x * WARPS_PER_BLOCK + warp;   // one warp per row

    const int ct0 = cand_txt[2 * b + 0];
    const int ct1 = cand_txt[2 * b + 1];
    const int ci0 = cand_img[2 * b + 0];
    const int ci1 = cand_img[2 * b + 1];

    // 6 source rows, each lane covers element (c*32+lane) per chunk c
    const float4* p[NSRC];
    p[0] = (const float4*)(img + (size_t)b   * DD) + lane;
    p[1] = (const float4*)(txt + (size_t)b   * DD) + lane;
    p[2] = (const float4*)(txt + (size_t)ct0 * DD) + lane;
    p[3] = (const float4*)(txt + (size_t)ct1 * DD) + lane;
    p[4] = (const float4*)(img + (size_t)ci0 * DD) + lane;
    p[5] = (const float4*)(img + (size_t)ci1 * DD) + lane;

    // per-warp, per-lane smem slots: no cross-lane reads, no barriers needed
    // index: ((warp*STAGES + stage)*NSRC + src)*32 + lane
    uint32_t slot[STAGES];   // smem byte address of this lane's src0 slot per stage
    #pragma unroll
    for (int s = 0; s < STAGES; s++)
        slot[s] = (uint32_t)__cvta_generic_to_shared(
            &sbuf[((warp * STAGES + s) * NSRC) * 32 + lane]);

    // prologue: stage chunks 0 and 1
    #pragma unroll
    for (int s = 0; s < 2; s++) {
        #pragma unroll
        for (int k = 0; k < NSRC; k++)
            cp16(slot[s] + k * 512, p[k] + s * 32);
        cp_commit();
    }

    float acc[NACC];
    #pragma unroll
    for (int a = 0; a < NACC; a++) acc[a] = 0.0f;

    #pragma unroll
    for (int c = 0; c < CHUNKS; c++) {
        cp_wait1();   // chunk c landed (<=1 pending group = chunk c+1)

        const int cur = c % STAGES;
        const float4* sp = (const float4*)__cvta_shared_to_generic((size_t)slot[cur]);
        const float4 vi  = sp[0 * 32];
        const float4 vt  = sp[1 * 32];
        const float4 vt0 = sp[2 * 32];
        const float4 vt1 = sp[3 * 32];
        const float4 vi0 = sp[4 * 32];
        const float4 vi1 = sp[5 * 32];

        // stage chunk c+2 into buffer (c+2)%3 (distinct from cur and c+1's)
        if (c + 2 < CHUNKS) {
            const int nst = (c + 2) % STAGES;
            #pragma unroll
            for (int k = 0; k < NSRC; k++)
                cp16(slot[nst] + k * 512, p[k] + (c + 2) * 32);
        }
        cp_commit();   // always commit (possibly empty) to keep group count uniform

        // 0: |img_b|^2   1: |txt_b|^2   2: dot(img_b, txt_b)
        // 3: dot(img_b, txt_c0)  4: |txt_c0|^2
        // 5: dot(img_b, txt_c1)  6: |txt_c1|^2
        // 7: dot(txt_b, img_e0)  8: |img_e0|^2
        // 9: dot(txt_b, img_e1) 10: |img_e1|^2
        acc[0]  += vi.x*vi.x  + vi.y*vi.y  + vi.z*vi.z  + vi.w*vi.w;
        acc[1]  += vt.x*vt.x  + vt.y*vt.y  + vt.z*vt.z  + vt.w*vt.w;
        acc[2]  += vi.x*vt.x  + vi.y*vt.y  + vi.z*vt.z  + vi.w*vt.w;
        acc[3]  += vi.x*vt0.x + vi.y*vt0.y + vi.z*vt0.z + vi.w*vt0.w;
        acc[4]  += vt0.x*vt0.x+ vt0.y*vt0.y+ vt0.z*vt0.z+ vt0.w*vt0.w;
        acc[5]  += vi.x*vt1.x + vi.y*vt1.y + vi.z*vt1.z + vi.w*vt1.w;
        acc[6]  += vt1.x*vt1.x+ vt1.y*vt1.y+ vt1.z*vt1.z+ vt1.w*vt1.w;
        acc[7]  += vt.x*vi0.x + vt.y*vi0.y + vt.z*vi0.z + vt.w*vi0.w;
        acc[8]  += vi0.x*vi0.x+ vi0.y*vi0.y+ vi0.z*vi0.z+ vi0.w*vi0.w;
        acc[9]  += vt.x*vi1.x + vt.y*vi1.y + vt.z*vi1.z + vt.w*vi1.w;
        acc[10] += vi1.x*vi1.x+ vi1.y*vi1.y+ vi1.z*vi1.z+ vi1.w*vi1.w;
    }

    // single warp-level reduction per row
    #pragma unroll
    for (int a = 0; a < NACC; a++) {
        float x = acc[a];
        #pragma unroll
        for (int off = 16; off > 0; off >>= 1)
            x += __shfl_xor_sync(0xFFFFFFFFu, x, off);
        acc[a] = x;
    }

    __shared__ float sloss[WARPS_PER_BLOCK];

    if (lane == 0) {
        const float ni    = sqrtf(acc[0]);   // |img_b|
        const float nt    = sqrtf(acc[1]);   // |txt_b|
        const float nprod = ni * nt;

        const float sim      = acc[2] / nprod;                      // unclamped
        const float pos_dist = 1.0f - acc[2] / fmaxf(nprod, EPSF);  // clamped

        const float dT0 = 1.0f - acc[3] / fmaxf(ni * sqrtf(acc[4]), EPSF);
        const float dT1 = 1.0f - acc[5] / fmaxf(ni * sqrtf(acc[6]), EPSF);
        const float i2t_neg = fminf(dT0, dT1);   // `d1<=d0` tie-break == min

        const float dI0 = 1.0f - acc[7] / fmaxf(nt * sqrtf(acc[8]),  EPSF);
        const float dI1 = 1.0f - acc[9] / fmaxf(nt * sqrtf(acc[10]), EPSF);
        const float t2i_neg = fminf(dI0, dI1);

        const float i2t_trip = fmaxf(pos_dist - i2t_neg + MARGIN, 0.0f);
        const float t2i_trip = fmaxf(pos_dist - t2i_neg + MARGIN, 0.0f);

        // outputs: [loss, i2t_cosine(B), t2i_cosine(B)]; cosines identical pair
        out[1 + b]      = sim;
        out[1 + BB + b] = sim;
        sloss[warp] = (i2t_trip + t2i_trip) * (1.0f / (float)BB);
    }

    __syncthreads();
    if (tid == 0) {
        float s = 0.0f;
        #pragma unroll
        for (int w = 0; w < WARPS_PER_BLOCK; w++) s += sloss[w];
        atomicAdd(out, s);   // 512 same-address atomics total
    }
}

extern "C" void kernel_launch(void* const* d_in, const int* in_sizes, int n_in,
                              void* d_out, int out_size) {
    const float* img      = (const float*)d_in[0];
    const float* txt      = (const float*)d_in[1];
    // d_in[2] = labels (identity anchors, unused), d_in[3] = locations (unused)
    const int*   cand_img = (const int*)d_in[4];
    const int*   cand_txt = (const int*)d_in[5];
    float* out = (float*)d_out;

    static int smem_configured = 0;
    if (!smem_configured) {
        cudaFuncSetAttribute(contrastive_kernel,
                             cudaFuncAttributeMaxDynamicSharedMemorySize,
                             SMEM_BYTES);
        smem_configured = 1;
    }

    init_out_kernel<<<1, 1>>>(out);
    contrastive_kernel<<<NBLOCKS, THREADS, SMEM_BYTES>>>(img, txt, cand_img,
                                                         cand_txt, out);
}